// round 5
// baseline (speedup 1.0000x reference)
#include <cuda_runtime.h>
#include <cuda_bf16.h>
#include <math.h>

// Problem constants (fixed shapes per reference)
#define NN    100000      // total nodes
#define BB    50          // graphs
#define NPG   2000        // nodes per graph
#define FF    64          // input features
#define HH    64          // hidden
#define EE    1600000     // edges
#define NBANDS 3
#define NZF   2400000     // framelet nnz
#define NZPG  (NZF / BB)  // 48000 nz per graph (graph-contiguous)
#define NCC   10          // classes

#define SCAN_ELEMS 1024
#define SCAN_NBLK  ((NN + SCAN_ELEMS - 1) / SCAN_ELEMS)   // 98

// ---------------- static scratch (no allocation allowed) ----------------
__device__ __align__(256) float g_bufA[(size_t)NN * HH];
__device__ __align__(256) float g_bufB[(size_t)NN * HH];
__device__ __align__(256) float g_dinv[NN];
__device__ __align__(256) int   g_cnt[NN];
__device__ __align__(256) int   g_off[NN];
__device__ __align__(256) int   g_cur[NN];
__device__ __align__(256) int   g_col[EE];
__device__ __align__(256) int   g_bsum[SCAN_NBLK];
__device__ __align__(256) float g_w[(size_t)NN * NBANDS];

// ---------------- streams/events for intra-graph parallelism ----------------
struct StreamPack {
    cudaStream_t sB = nullptr, sC = nullptr;
    cudaEvent_t  ev0 = nullptr, evB = nullptr, evC = nullptr;
    bool ok = false;
    StreamPack() {
        if (cudaStreamCreateWithFlags(&sB, cudaStreamNonBlocking) != cudaSuccess) return;
        if (cudaStreamCreateWithFlags(&sC, cudaStreamNonBlocking) != cudaSuccess) return;
        if (cudaEventCreateWithFlags(&ev0, cudaEventDisableTiming) != cudaSuccess) return;
        if (cudaEventCreateWithFlags(&evB, cudaEventDisableTiming) != cudaSuccess) return;
        if (cudaEventCreateWithFlags(&evC, cudaEventDisableTiming) != cudaSuccess) return;
        ok = true;
    }
};
static StreamPack g_sp;

// ---------------- histogram of edge rows (4 edges / thread) ----------------
__global__ void hist_kernel(const int* __restrict__ row) {
    int i = (blockIdx.x * blockDim.x + threadIdx.x) * 4;
    if (i + 3 < EE) {
        int4 r = *(const int4*)(row + i);
        atomicAdd(&g_cnt[r.x], 1);
        atomicAdd(&g_cnt[r.y], 1);
        atomicAdd(&g_cnt[r.z], 1);
        atomicAdd(&g_cnt[r.w], 1);
    } else {
        for (int j = i; j < EE; j++) atomicAdd(&g_cnt[row[j]], 1);
    }
}

// ---------------- scan phase 1: per-block sums + dinv ----------------
__global__ void scan_partial_kernel() {
    int t = threadIdx.x;
    int base = blockIdx.x * SCAN_ELEMS + t * 4;
    int4 v = make_int4(0, 0, 0, 0);
    bool in = (base < NN);     // NN % 4 == 0 -> full int4 whenever base < NN
    if (in) {
        v = *(const int4*)(g_cnt + base);
        float4 dv;
        dv.x = rsqrtf((float)(v.x + 1));
        dv.y = rsqrtf((float)(v.y + 1));
        dv.z = rsqrtf((float)(v.z + 1));
        dv.w = rsqrtf((float)(v.w + 1));
        *(float4*)(g_dinv + base) = dv;
    }
    int s = v.x + v.y + v.z + v.w;
    for (int d = 16; d > 0; d >>= 1) s += __shfl_down_sync(0xffffffff, s, d);
    __shared__ int ws[8];
    if ((t & 31) == 0) ws[t >> 5] = s;
    __syncthreads();
    if (t < 8) {
        int x = ws[t];
        for (int d = 4; d > 0; d >>= 1) x += __shfl_down_sync(0xff, x, d);
        if (t == 0) g_bsum[blockIdx.x] = x;
    }
}

// ---------------- scan phase 2 (fused): every block redundantly scans the 98
// block sums, then does its per-block exclusive scan -> g_off, g_cur ---------
__global__ void scan_final_kernel() {
    __shared__ int bo[128];
    int t = threadIdx.x;
    int lane = t & 31, warp = t >> 5;

    // inline mid-scan of block sums (exclusive), redundant per block
    if (t < 128) {
        int v = (t < SCAN_NBLK) ? g_bsum[t] : 0;
        bo[t] = v;
        __syncwarp();
    }
    __syncthreads();
    if (t < 128) {
        // Hillis-Steele over 128 entries using 4 warps
        for (int d = 1; d < 128; d <<= 1) {
            int u = (t >= d) ? bo[t - d] : 0;
            __syncthreads();
            bo[t] += u;
            __syncthreads();
        }
    } else {
        for (int d = 1; d < 128; d <<= 1) { __syncthreads(); __syncthreads(); }
    }
    __syncthreads();
    int blk_off = (blockIdx.x == 0) ? 0 : bo[blockIdx.x - 1];

    int base = blockIdx.x * SCAN_ELEMS + t * 4;
    int4 v = make_int4(0, 0, 0, 0);
    bool in = (base < NN);
    if (in) v = *(const int4*)(g_cnt + base);
    int s = v.x + v.y + v.z + v.w;
    int incl = s;
    for (int d = 1; d < 32; d <<= 1) {
        int u = __shfl_up_sync(0xffffffff, incl, d);
        if (lane >= d) incl += u;
    }
    __shared__ int wsum[8];
    if (lane == 31) wsum[warp] = incl;
    __syncthreads();
    __shared__ int woff[8];
    if (t < 8) {
        int x = wsum[t];
        int wincl = x;
        for (int d = 1; d < 8; d <<= 1) {
            int u = __shfl_up_sync(0xff, wincl, d);
            if (t >= d) wincl += u;
        }
        woff[t] = wincl - x;
    }
    __syncthreads();
    if (in) {
        int excl = (incl - s) + woff[warp] + blk_off;
        int4 o = make_int4(excl, excl + v.x, excl + v.x + v.y, excl + v.x + v.y + v.z);
        *(int4*)(g_off + base) = o;
        *(int4*)(g_cur + base) = o;
    }
}

// ---------------- bucket-scatter edges into CSR col list (4/thread) ----------
__global__ void scatter_kernel(const int* __restrict__ row, const int* __restrict__ col) {
    int i = (blockIdx.x * blockDim.x + threadIdx.x) * 4;
    if (i + 3 < EE) {
        int4 r = *(const int4*)(row + i);
        int4 c = *(const int4*)(col + i);
        int p0 = atomicAdd(&g_cur[r.x], 1);
        int p1 = atomicAdd(&g_cur[r.y], 1);
        int p2 = atomicAdd(&g_cur[r.z], 1);
        int p3 = atomicAdd(&g_cur[r.w], 1);
        g_col[p0] = c.x;
        g_col[p1] = c.y;
        g_col[p2] = c.z;
        g_col[p3] = c.w;
    } else {
        for (int j = i; j < EE; j++) {
            int pos = atomicAdd(&g_cur[row[j]], 1);
            g_col[pos] = col[j];
        }
    }
}

// ---------------- GEMM: Y = X @ W ----------------
__global__ void gemm64_kernel(const float* __restrict__ X, const float* __restrict__ W,
                              float* __restrict__ Y, int M) {
    __shared__ float Ws[64 * 64];
    __shared__ float Xs[64][65];
    int t = threadIdx.x;
    int row0 = blockIdx.x * 64;
    int rows = min(64, M - row0);

    for (int i = t; i < 1024; i += 256)
        ((float4*)Ws)[i] = ((const float4*)W)[i];
    for (int i = t; i < rows * 64; i += 256) {
        int r = i >> 6, c = i & 63;
        Xs[r][c] = X[(size_t)(row0 + r) * 64 + c];
    }
    __syncthreads();

    int r = t & 63;
    int cg = t >> 6;
    if (r < rows) {
        float acc[16];
#pragma unroll
        for (int j = 0; j < 16; j++) acc[j] = 0.0f;
#pragma unroll 8
        for (int k = 0; k < 64; k++) {
            float a = Xs[r][k];
            const float4* wr = (const float4*)(Ws + k * 64 + cg * 16);
#pragma unroll
            for (int j = 0; j < 4; j++) {
                float4 w = wr[j];
                acc[4 * j + 0] += a * w.x;
                acc[4 * j + 1] += a * w.y;
                acc[4 * j + 2] += a * w.z;
                acc[4 * j + 3] += a * w.w;
            }
        }
        float4* yp = (float4*)(Y + (size_t)(row0 + r) * 64 + cg * 16);
#pragma unroll
        for (int j = 0; j < 4; j++)
            yp[j] = make_float4(acc[4 * j], acc[4 * j + 1], acc[4 * j + 2], acc[4 * j + 3]);
    }
}

// ---------------- GCN aggregation + bias + relu ----------------
// warp per row, two 16-lane groups (float4 lanes, 256B/neighbor),
// unrolled x4 per group -> 4 outstanding row gathers.
__global__ void agg_kernel(const float* __restrict__ hin, float* __restrict__ hout,
                           const float* __restrict__ bias) {
    int warp = (blockIdx.x * blockDim.x + threadIdx.x) >> 5;
    if (warp >= NN) return;
    int lane = threadIdx.x & 31;
    int grp  = lane >> 4;
    int fo   = lane & 15;
    int row = warp;
    int off = g_off[row];
    int cnt = g_cnt[row];
    float4 a0 = make_float4(0.f, 0.f, 0.f, 0.f);
    float4 a1 = make_float4(0.f, 0.f, 0.f, 0.f);
    float4 a2 = make_float4(0.f, 0.f, 0.f, 0.f);
    float4 a3 = make_float4(0.f, 0.f, 0.f, 0.f);
    int k = grp;
    for (; k + 6 < cnt; k += 8) {
        int c0 = __ldg(&g_col[off + k]);
        int c1 = __ldg(&g_col[off + k + 2]);
        int c2 = __ldg(&g_col[off + k + 4]);
        int c3 = __ldg(&g_col[off + k + 6]);
        float d0 = __ldg(&g_dinv[c0]);
        float d1 = __ldg(&g_dinv[c1]);
        float d2 = __ldg(&g_dinv[c2]);
        float d3 = __ldg(&g_dinv[c3]);
        float4 v0 = *(const float4*)(hin + (size_t)c0 * 64 + fo * 4);
        float4 v1 = *(const float4*)(hin + (size_t)c1 * 64 + fo * 4);
        float4 v2 = *(const float4*)(hin + (size_t)c2 * 64 + fo * 4);
        float4 v3 = *(const float4*)(hin + (size_t)c3 * 64 + fo * 4);
        a0.x += d0 * v0.x; a0.y += d0 * v0.y; a0.z += d0 * v0.z; a0.w += d0 * v0.w;
        a1.x += d1 * v1.x; a1.y += d1 * v1.y; a1.z += d1 * v1.z; a1.w += d1 * v1.w;
        a2.x += d2 * v2.x; a2.y += d2 * v2.y; a2.z += d2 * v2.z; a2.w += d2 * v2.w;
        a3.x += d3 * v3.x; a3.y += d3 * v3.y; a3.z += d3 * v3.z; a3.w += d3 * v3.w;
    }
    for (; k < cnt; k += 2) {
        int c = __ldg(&g_col[off + k]);
        float d = __ldg(&g_dinv[c]);
        float4 v = *(const float4*)(hin + (size_t)c * 64 + fo * 4);
        a0.x += d * v.x; a0.y += d * v.y; a0.z += d * v.z; a0.w += d * v.w;
    }
    float di = g_dinv[row];
    if (grp == 0) {  // self loop (weight dinv[row]) once
        float4 v = *(const float4*)(hin + (size_t)row * 64 + fo * 4);
        a0.x += di * v.x; a0.y += di * v.y; a0.z += di * v.z; a0.w += di * v.w;
    }
    a0.x += a1.x + a2.x + a3.x;
    a0.y += a1.y + a2.y + a3.y;
    a0.z += a1.z + a2.z + a3.z;
    a0.w += a1.w + a2.w + a3.w;
    a0.x += __shfl_down_sync(0xffffffff, a0.x, 16);
    a0.y += __shfl_down_sync(0xffffffff, a0.y, 16);
    a0.z += __shfl_down_sync(0xffffffff, a0.z, 16);
    a0.w += __shfl_down_sync(0xffffffff, a0.w, 16);
    if (grp == 0) {
        float4 b = *(const float4*)(bias + fo * 4);
        float4 o;
        o.x = fmaxf(di * a0.x + b.x, 0.f);
        o.y = fmaxf(di * a0.y + b.y, 0.f);
        o.z = fmaxf(di * a0.z + b.z, 0.f);
        o.w = fmaxf(di * a0.w + b.w, 0.f);
        *(float4*)(hout + (size_t)row * 64 + fo * 4) = o;
    }
}

// ---------------- framelet node-band weights (independent of GCN path) -------
__global__ void __launch_bounds__(1024, 1)
frame_kernel(const int* __restrict__ frow, const int* __restrict__ fcol,
             const float* __restrict__ fval, const int* __restrict__ dindex) {
    __shared__ float ws[NPG * NBANDS];   // 24 KB
    int g = blockIdx.x;
    int t = threadIdx.x;
    int node0 = g * NPG;
    for (int i = t; i < NPG * NBANDS; i += 1024) ws[i] = 0.0f;
    __syncthreads();
    int base = g * NZPG;
    for (int i = t; i < NZPG; i += 1024) {
        int k = base + i;
        int band = __ldg(&dindex[frow[k]]);
        int c = fcol[k] - node0;
        atomicAdd(&ws[c * NBANDS + band], fval[k]);
    }
    __syncthreads();
    float* dst = g_w + (size_t)g * NPG * NBANDS;
    for (int i = t; i < (NPG * NBANDS) / 4; i += 1024)
        ((float4*)dst)[i] = ((const float4*)ws)[i];
}

// ---------------- pool + MLP head ----------------
__global__ void __launch_bounds__(1024, 1)
tail_kernel(const float* __restrict__ h,
            const float* __restrict__ fcW1, const float* __restrict__ fcb1,
            const float* __restrict__ fcW2, const float* __restrict__ fcb2,
            float* __restrict__ out) {
    __shared__ float ws[NPG * NBANDS];         // 24 KB
    __shared__ float partial[5 * NBANDS * HH]; // 3.75 KB
    __shared__ float xs[NBANDS * HH];
    __shared__ float hid[HH];

    int g = blockIdx.x;
    int t = threadIdx.x;
    int node0 = g * NPG;

    const float* src = g_w + (size_t)g * NPG * NBANDS;
    for (int i = t; i < (NPG * NBANDS) / 4; i += 1024)
        ((float4*)ws)[i] = ((const float4*)src)[i];
    __syncthreads();

    if (t < 960) {
        int grp = t / 192;
        int p   = t % 192;
        int band = p / 64, f = p % 64;
        float acc = 0.0f;
        for (int nd = grp; nd < NPG; nd += 5)
            acc += ws[nd * NBANDS + band] * __ldg(&h[(size_t)(node0 + nd) * 64 + f]);
        partial[grp * 192 + p] = acc;
    }
    __syncthreads();
    if (t < 192) {
        xs[t] = partial[t] + partial[192 + t] + partial[384 + t]
              + partial[576 + t] + partial[768 + t];
    }
    __syncthreads();

    if (t < HH) {
        float acc = fcb1[t];
#pragma unroll 8
        for (int k = 0; k < NBANDS * HH; k++)
            acc += xs[k] * fcW1[k * HH + t];
        hid[t] = fmaxf(acc, 0.0f);
    }
    __syncthreads();
    if (t < NCC) {
        float o = fcb2[t];
#pragma unroll 8
        for (int k = 0; k < HH; k++)
            o += hid[k] * fcW2[k * NCC + t];
        out[g * NCC + t] = o;
    }
}

// ---------------- launch ----------------
extern "C" void kernel_launch(void* const* d_in, const int* in_sizes, int n_in,
                              void* d_out, int out_size) {
    const float* x         = (const float*)d_in[0];
    const int*   ei        = (const int*)  d_in[1];   // [2, E]: rows then cols
    const int*   frow      = (const int*)  d_in[3];
    const int*   fcol      = (const int*)  d_in[4];
    const float* fval      = (const float*)d_in[5];
    const int*   dindex    = (const int*)  d_in[6];
    const float* W1        = (const float*)d_in[8];
    const float* b1        = (const float*)d_in[9];
    const float* W2        = (const float*)d_in[10];
    const float* b2        = (const float*)d_in[11];
    const float* fcW1      = (const float*)d_in[12];
    const float* fcb1      = (const float*)d_in[13];
    const float* fcW2      = (const float*)d_in[14];
    const float* fcb2      = (const float*)d_in[15];
    float* out = (float*)d_out;

    const int* erow = ei;
    const int* ecol = ei + EE;

    float* bufA; cudaGetSymbolAddress((void**)&bufA, g_bufA);
    float* bufB; cudaGetSymbolAddress((void**)&bufB, g_bufB);
    int*   cnt;  cudaGetSymbolAddress((void**)&cnt,  g_cnt);

    bool par = g_sp.ok;

    if (par) {
        cudaEventRecord(g_sp.ev0, 0);
        cudaStreamWaitEvent(g_sp.sB, g_sp.ev0, 0);
        cudaStreamWaitEvent(g_sp.sC, g_sp.ev0, 0);
        gemm64_kernel<<<(NN + 63) / 64, 256, 0, g_sp.sB>>>(x, W1, bufA, NN);
        cudaEventRecord(g_sp.evB, g_sp.sB);
        frame_kernel<<<BB, 1024, 0, g_sp.sC>>>(frow, fcol, fval, dindex);
        cudaEventRecord(g_sp.evC, g_sp.sC);
    }

    // CSR build on main stream
    cudaMemsetAsync(cnt, 0, NN * sizeof(int), 0);
    hist_kernel<<<(EE / 4 + 255) / 256, 256>>>(erow);
    scan_partial_kernel<<<SCAN_NBLK, 256>>>();
    scan_final_kernel<<<SCAN_NBLK, 256>>>();
    scatter_kernel<<<(EE / 4 + 255) / 256, 256>>>(erow, ecol);

    if (par) {
        cudaStreamWaitEvent(0, g_sp.evB, 0);   // join gemm1
    } else {
        gemm64_kernel<<<(NN + 63) / 64, 256>>>(x, W1, bufA, NN);
    }

    // GCN layer 1 aggregation
    agg_kernel<<<(NN * 32 + 255) / 256, 256>>>(bufA, bufB, b1);

    // GCN layer 2
    gemm64_kernel<<<(NN + 63) / 64, 256>>>(bufB, W2, bufA, NN);
    agg_kernel<<<(NN * 32 + 255) / 256, 256>>>(bufA, bufB, b2);

    if (par) {
        cudaStreamWaitEvent(0, g_sp.evC, 0);   // join framelet weights
    } else {
        frame_kernel<<<BB, 1024>>>(frow, fcol, fval, dindex);
    }

    // pool + MLP head
    tail_kernel<<<BB, 1024>>>(bufB, fcW1, fcb1, fcW2, fcb2, out);
}